// round 2
// baseline (speedup 1.0000x reference)
#include <cuda_runtime.h>
#include <cuda_bf16.h>
#include <cstdint>

#define BB 128
#define SS 256
#define II 512
#define HH 1024
#define H3 3072
#define SA 24  // padded smem stride (bf16) -> conflict-free fragment loads

// ---------------- device scratch ----------------
__device__ __align__(16) __nv_bfloat16 g_xhi[(size_t)BB * SS * II];
__device__ __align__(16) __nv_bfloat16 g_xlo[(size_t)BB * SS * II];
__device__ __align__(16) __nv_bfloat16 g_wih_hi[H3 * II];
__device__ __align__(16) __nv_bfloat16 g_wih_lo[H3 * II];
__device__ __align__(16) __nv_bfloat16 g_whh_hi[H3 * HH];
__device__ __align__(16) __nv_bfloat16 g_whh_lo[H3 * HH];
__device__ __align__(16) float g_Xg[(size_t)SS * BB * H3];
__device__ __align__(16) float g_sx[SS * BB];
__device__ __align__(16) float g_hfp[2][BB * HH];
__device__ __align__(16) __nv_bfloat16 g_hhi[2][BB * HH];
__device__ __align__(16) __nv_bfloat16 g_hlo[2][BB * HH];
__device__ __align__(16) float g_ghp[6][(size_t)BB * H3];
__device__ float g_score[2][BB];

__device__ __forceinline__ void mma16816(float* c, const uint32_t* a, uint32_t b0, uint32_t b1) {
    asm volatile(
        "mma.sync.aligned.m16n8k16.row.col.f32.bf16.bf16.f32 "
        "{%0,%1,%2,%3}, {%4,%5,%6,%7}, {%8,%9}, {%0,%1,%2,%3};\n"
        : "+f"(c[0]), "+f"(c[1]), "+f"(c[2]), "+f"(c[3])
        : "r"(a[0]), "r"(a[1]), "r"(a[2]), "r"(a[3]), "r"(b0), "r"(b1));
}

// ---------------- init: state slot 1 (input of step 0) ----------------
__global__ void k_init() {
    int i = blockIdx.x * blockDim.x + threadIdx.x;
    if (i < BB * HH) {
        g_hfp[1][i] = 0.f;
        g_hhi[1][i] = __float2bfloat16(0.f);
        g_hlo[1][i] = __float2bfloat16(0.f);
    }
    if (i < BB) g_score[1][i] = 0.f;
}

// ---------------- fp32 -> bf16 hi/lo split ----------------
__global__ void k_split(const float* __restrict__ src, int n, int which) {
    __nv_bfloat16 *hi, *lo;
    if (which == 0)      { hi = g_xhi;    lo = g_xlo; }
    else if (which == 1) { hi = g_wih_hi; lo = g_wih_lo; }
    else                 { hi = g_whh_hi; lo = g_whh_lo; }
    int i = blockIdx.x * blockDim.x + threadIdx.x;
    if (i < n) {
        float v = src[i];
        __nv_bfloat16 h = __float2bfloat16(v);
        hi[i] = h;
        lo[i] = __float2bfloat16(v - __bfloat162float(h));
    }
}

// ---------------- sx[t][b] = x[b,t,:] . W_att[0:I] ----------------
__global__ void k_sx(const float* __restrict__ x, const float* __restrict__ Watt) {
    int gw = (blockIdx.x * blockDim.x + threadIdx.x) >> 5;
    int lane = threadIdx.x & 31;
    if (gw >= SS * BB) return;
    int t = gw >> 7, b = gw & 127;
    const float* xr = x + ((size_t)b * SS + t) * II;
    float s = 0.f;
    for (int k = lane; k < II; k += 32) s += xr[k] * Watt[k];
    #pragma unroll
    for (int o = 16; o; o >>= 1) s += __shfl_xor_sync(0xffffffffu, s, o);
    if (!lane) g_sx[gw] = s;
}

// ---------------- precompute Xg[t][b][:] = x_t @ W_ih^T (3-way split) ----------------
// grid (24 n-tiles of 128, 256 t). block 256 thr, warps 4(m)x2(n).
__global__ __launch_bounds__(256) void k_xg() {
    __shared__ __align__(16) __nv_bfloat16 As[2][128 * SA];
    __shared__ __align__(16) __nv_bfloat16 Bs[2][128 * SA];
    const int nblk = blockIdx.x, t = blockIdx.y;
    const int tid = threadIdx.x, w = tid >> 5, lane = tid & 31;
    const int wm = w & 3, wn = w >> 2, gid = lane >> 2, tig = lane & 3;
    const int ar = tid >> 1, ah = tid & 1;
    const size_t a_base = ((size_t)ar * SS + t) * II + ah * 8;          // A row = batch
    const size_t b_base = ((size_t)(nblk * 128 + ar)) * II + ah * 8;    // W_ih row

    float acc[2][8][4];
    #pragma unroll
    for (int i = 0; i < 2; ++i)
        #pragma unroll
        for (int j = 0; j < 8; ++j) { acc[i][j][0]=acc[i][j][1]=acc[i][j][2]=acc[i][j][3]=0.f; }

    *(uint4*)&As[0][ar * SA + ah * 8] = *(const uint4*)(g_xhi + a_base);
    *(uint4*)&Bs[0][ar * SA + ah * 8] = *(const uint4*)(g_wih_hi + b_base);
    __syncthreads();

    for (int it = 0; it < 96; ++it) {
        const int cur = it & 1;
        uint4 va, vb;
        const bool pf = (it + 1 < 96);
        if (pf) {
            int it2 = it + 1, seg = it2 >> 5, kk = (it2 & 31) << 4;
            const __nv_bfloat16* pa = (seg == 1) ? g_xlo : g_xhi;
            const __nv_bfloat16* pb = (seg == 2) ? g_wih_lo : g_wih_hi;
            va = *(const uint4*)(pa + a_base + kk);
            vb = *(const uint4*)(pb + b_base + kk);
        }
        uint32_t af[2][4];
        #pragma unroll
        for (int mt = 0; mt < 2; ++mt) {
            int r0 = wm * 32 + mt * 16;
            af[mt][0] = *(const uint32_t*)&As[cur][(r0 + gid) * SA + 2 * tig];
            af[mt][1] = *(const uint32_t*)&As[cur][(r0 + gid + 8) * SA + 2 * tig];
            af[mt][2] = *(const uint32_t*)&As[cur][(r0 + gid) * SA + 2 * tig + 8];
            af[mt][3] = *(const uint32_t*)&As[cur][(r0 + gid + 8) * SA + 2 * tig + 8];
        }
        #pragma unroll
        for (int nt = 0; nt < 8; ++nt) {
            int n0 = (wn * 8 + nt) * 8;
            uint32_t b0 = *(const uint32_t*)&Bs[cur][(n0 + gid) * SA + 2 * tig];
            uint32_t b1 = *(const uint32_t*)&Bs[cur][(n0 + gid) * SA + 2 * tig + 8];
            mma16816(acc[0][nt], af[0], b0, b1);
            mma16816(acc[1][nt], af[1], b0, b1);
        }
        __syncthreads();
        if (pf) {
            int nb = (it + 1) & 1;
            *(uint4*)&As[nb][ar * SA + ah * 8] = va;
            *(uint4*)&Bs[nb][ar * SA + ah * 8] = vb;
            __syncthreads();
        }
    }
    #pragma unroll
    for (int mt = 0; mt < 2; ++mt)
        #pragma unroll
        for (int nt = 0; nt < 8; ++nt) {
            int m = wm * 32 + mt * 16 + gid;                   // batch row
            int n = nblk * 128 + wn * 64 + nt * 8 + 2 * tig;
            size_t base = ((size_t)t * BB + m) * H3 + n;
            g_Xg[base]            = acc[mt][nt][0];
            g_Xg[base + 1]        = acc[mt][nt][1];
            g_Xg[base + 8 * H3]   = acc[mt][nt][2];
            g_Xg[base + 8 * H3+1] = acc[mt][nt][3];
        }
}

// ---------------- per-step: gh partials = h @ W_hh^T ----------------
// grid (24 n-tiles of 128, 6 parts = 3 seg x 2 k-halves)
__global__ __launch_bounds__(256) void k_gh(int t) {
    __shared__ __align__(16) __nv_bfloat16 As[2][128 * SA];
    __shared__ __align__(16) __nv_bfloat16 Bs[2][128 * SA];
    const int nblk = blockIdx.x, part = blockIdx.y;
    const int seg = part >> 1, k0 = (part & 1) * 512;
    const int pr = (t + 1) & 1;
    const __nv_bfloat16* Ap = (seg == 1) ? g_hlo[pr] : g_hhi[pr];
    const __nv_bfloat16* Bp = (seg == 2) ? g_whh_lo : g_whh_hi;

    const int tid = threadIdx.x, w = tid >> 5, lane = tid & 31;
    const int wm = w & 3, wn = w >> 2, gid = lane >> 2, tig = lane & 3;
    const int ar = tid >> 1, ah = tid & 1;
    const size_t a_base = (size_t)ar * HH + k0 + ah * 8;
    const size_t b_base = (size_t)(nblk * 128 + ar) * HH + k0 + ah * 8;

    float acc[2][8][4];
    #pragma unroll
    for (int i = 0; i < 2; ++i)
        #pragma unroll
        for (int j = 0; j < 8; ++j) { acc[i][j][0]=acc[i][j][1]=acc[i][j][2]=acc[i][j][3]=0.f; }

    *(uint4*)&As[0][ar * SA + ah * 8] = *(const uint4*)(Ap + a_base);
    *(uint4*)&Bs[0][ar * SA + ah * 8] = *(const uint4*)(Bp + b_base);
    __syncthreads();

    for (int it = 0; it < 32; ++it) {
        const int cur = it & 1;
        uint4 va, vb;
        const bool pf = (it + 1 < 32);
        if (pf) {
            int kk = (it + 1) << 4;
            va = *(const uint4*)(Ap + a_base + kk);
            vb = *(const uint4*)(Bp + b_base + kk);
        }
        uint32_t af[2][4];
        #pragma unroll
        for (int mt = 0; mt < 2; ++mt) {
            int r0 = wm * 32 + mt * 16;
            af[mt][0] = *(const uint32_t*)&As[cur][(r0 + gid) * SA + 2 * tig];
            af[mt][1] = *(const uint32_t*)&As[cur][(r0 + gid + 8) * SA + 2 * tig];
            af[mt][2] = *(const uint32_t*)&As[cur][(r0 + gid) * SA + 2 * tig + 8];
            af[mt][3] = *(const uint32_t*)&As[cur][(r0 + gid + 8) * SA + 2 * tig + 8];
        }
        #pragma unroll
        for (int nt = 0; nt < 8; ++nt) {
            int n0 = (wn * 8 + nt) * 8;
            uint32_t b0 = *(const uint32_t*)&Bs[cur][(n0 + gid) * SA + 2 * tig];
            uint32_t b1 = *(const uint32_t*)&Bs[cur][(n0 + gid) * SA + 2 * tig + 8];
            mma16816(acc[0][nt], af[0], b0, b1);
            mma16816(acc[1][nt], af[1], b0, b1);
        }
        __syncthreads();
        if (pf) {
            int nb = (it + 1) & 1;
            *(uint4*)&As[nb][ar * SA + ah * 8] = va;
            *(uint4*)&Bs[nb][ar * SA + ah * 8] = vb;
            __syncthreads();
        }
    }
    float* out = g_ghp[part];
    #pragma unroll
    for (int mt = 0; mt < 2; ++mt)
        #pragma unroll
        for (int nt = 0; nt < 8; ++nt) {
            int m = wm * 32 + mt * 16 + gid;
            int n = nblk * 128 + wn * 64 + nt * 8 + 2 * tig;
            size_t base = (size_t)m * H3 + n;
            out[base]            = acc[mt][nt][0];
            out[base + 1]        = acc[mt][nt][1];
            out[base + 8 * H3]   = acc[mt][nt][2];
            out[base + 8 * H3+1] = acc[mt][nt][3];
        }
}

// ---------------- per-step update: softmax + GRU ----------------
// grid 128 (one block per batch row), 256 threads, 4 j per thread.
__global__ __launch_bounds__(256) void k_u(int t, const float* __restrict__ Watt,
                                           const float* __restrict__ b_ih,
                                           const float* __restrict__ b_hh,
                                           float* __restrict__ out, long long out_sz) {
    const int b = blockIdx.x, tid = threadIdx.x;
    const int pin = (t + 1) & 1, pout = t & 1;
    __shared__ float sc[BB], red[BB], wsum[8];

    if (tid < BB) {
        float v = g_score[pin][tid] + g_sx[t * BB + tid];
        sc[tid] = v;
        red[tid] = v;
    }
    __syncthreads();
    for (int s = 64; s; s >>= 1) { if (tid < s) red[tid] = fmaxf(red[tid], red[tid + s]); __syncthreads(); }
    float mx = red[0];
    __syncthreads();
    if (tid < BB) red[tid] = expf(sc[tid] - mx);
    __syncthreads();
    for (int s = 64; s; s >>= 1) { if (tid < s) red[tid] += red[tid + s]; __syncthreads(); }
    const float att = expf(sc[b] - mx) / red[0];

    const int j = tid * 4;
    const size_t rowb = (size_t)b * H3;
    float4 gr = make_float4(0, 0, 0, 0), gz = gr, gn = gr;
    #pragma unroll
    for (int c = 0; c < 6; ++c) {
        float4 v;
        v = *(const float4*)&g_ghp[c][rowb + j];          gr.x+=v.x; gr.y+=v.y; gr.z+=v.z; gr.w+=v.w;
        v = *(const float4*)&g_ghp[c][rowb + HH + j];     gz.x+=v.x; gz.y+=v.y; gz.z+=v.z; gz.w+=v.w;
        v = *(const float4*)&g_ghp[c][rowb + 2*HH + j];   gn.x+=v.x; gn.y+=v.y; gn.z+=v.z; gn.w+=v.w;
    }
    const size_t xgb = ((size_t)t * BB + b) * H3;
    float4 xr = *(const float4*)&g_Xg[xgb + j];
    float4 xz = *(const float4*)&g_Xg[xgb + HH + j];
    float4 xn = *(const float4*)&g_Xg[xgb + 2*HH + j];
    float4 hp = *(const float4*)&g_hfp[pin][(size_t)b * HH + j];

    float hn[4], hdot = 0.f;
    #pragma unroll
    for (int u = 0; u < 4; ++u) {
        float gir = att * ((&xr.x)[u]) + b_ih[j + u];
        float giz = att * ((&xz.x)[u]) + b_ih[HH + j + u];
        float gin = att * ((&xn.x)[u]) + b_ih[2*HH + j + u];
        float ghr = (&gr.x)[u] + b_hh[j + u];
        float ghz = (&gz.x)[u] + b_hh[HH + j + u];
        float ghn = (&gn.x)[u] + b_hh[2*HH + j + u];
        float r = 1.f / (1.f + expf(-(gir + ghr)));
        float z = 1.f / (1.f + expf(-(giz + ghz)));
        float n = tanhf(gin + r * ghn);
        float h = (1.f - z) * n + z * (&hp.x)[u];
        hn[u] = h;
        hdot += h * Watt[II + j + u];
    }
    // outputs [B,S,H]
    *(float4*)&out[((size_t)b * SS + t) * HH + j] = make_float4(hn[0], hn[1], hn[2], hn[3]);
    if (t == SS - 1 && out_sz >= (long long)BB * SS * HH + BB * HH)
        *(float4*)&out[(size_t)BB * SS * HH + (size_t)b * HH + j] = make_float4(hn[0], hn[1], hn[2], hn[3]);
    // next-step state
    *(float4*)&g_hfp[pout][(size_t)b * HH + j] = make_float4(hn[0], hn[1], hn[2], hn[3]);
    __nv_bfloat16 hi[4], lo[4];
    #pragma unroll
    for (int u = 0; u < 4; ++u) {
        hi[u] = __float2bfloat16(hn[u]);
        lo[u] = __float2bfloat16(hn[u] - __bfloat162float(hi[u]));
    }
    *(uint2*)&g_hhi[pout][(size_t)b * HH + j] = *(uint2*)hi;
    *(uint2*)&g_hlo[pout][(size_t)b * HH + j] = *(uint2*)lo;

    // score dot for next step
    #pragma unroll
    for (int o = 16; o; o >>= 1) hdot += __shfl_xor_sync(0xffffffffu, hdot, o);
    if ((tid & 31) == 0) wsum[tid >> 5] = hdot;
    __syncthreads();
    if (tid == 0) {
        float s = 0.f;
        #pragma unroll
        for (int i = 0; i < 8; ++i) s += wsum[i];
        g_score[pout][b] = s;
    }
}

// ---------------- launch ----------------
extern "C" void kernel_launch(void* const* d_in, const int* in_sizes, int n_in,
                              void* d_out, int out_size) {
    const float* x    = (const float*)d_in[0];
    const float* Watt = (const float*)d_in[1];
    const float* b_ih = (const float*)d_in[5];
    const float* b_hh = (const float*)d_in[6];
    const float* Wih  = (const float*)d_in[3];
    const float* Whh  = (const float*)d_in[4];
    float* out = (float*)d_out;

    k_split<<<(BB * SS * II + 255) / 256, 256>>>(x, BB * SS * II, 0);
    k_split<<<(H3 * II + 255) / 256, 256>>>(Wih, H3 * II, 1);
    k_split<<<(H3 * HH + 255) / 256, 256>>>(Whh, H3 * HH, 2);
    k_sx<<<4096, 256>>>(x, Watt);
    k_init<<<512, 256>>>();
    k_xg<<<dim3(24, 256), 256>>>();
    for (int t = 0; t < SS; ++t) {
        k_gh<<<dim3(24, 6), 256>>>(t);
        k_u<<<BB, 256>>>(t, Watt, b_ih, b_hh, out, (long long)out_size);
    }
}